// round 8
// baseline (speedup 1.0000x reference)
#include <cuda_runtime.h>

#define NB 4
#define NR 2
#define NREF 4
#define IH 320
#define IW 320
#define HW (IH*IW)
#define NPIX (NB*NR*HW)
#define NIMG (NB*NREF)

// Per-render-camera: M = inv(R)*inv(K) (9 floats) then v = inv(R)*t (3 floats)
__device__ float g_renderM[NB*NR][12];
// Per-(b,ref): P = K_ref*R_ref (9) then s = K_ref*t_ref (3)
__device__ float g_refP[NB*NREF][12];
// Channel-interleaved copy of image_ref: (img, y, x) -> float4(r,g,b,0)
__device__ float4 g_img4[NIMG*HW];

__device__ __forceinline__ void inv3(const float* a, float* o) {
    float c00 = a[4]*a[8] - a[5]*a[7];
    float c10 = a[5]*a[6] - a[3]*a[8];
    float c20 = a[3]*a[7] - a[4]*a[6];
    float det = a[0]*c00 + a[1]*c10 + a[2]*c20;
    float id  = 1.0f/det;
    o[0] = c00*id;
    o[1] = (a[2]*a[7] - a[1]*a[8])*id;
    o[2] = (a[1]*a[5] - a[2]*a[4])*id;
    o[3] = c10*id;
    o[4] = (a[0]*a[8] - a[2]*a[6])*id;
    o[5] = (a[2]*a[3] - a[0]*a[5])*id;
    o[6] = c20*id;
    o[7] = (a[1]*a[6] - a[0]*a[7])*id;
    o[8] = (a[0]*a[4] - a[1]*a[3])*id;
}

__device__ __forceinline__ void precompute_thread(
    int t,
    const float* __restrict__ camK,  const float* __restrict__ camW,
    const float* __restrict__ camKr, const float* __restrict__ camWr)
{
    if (t < NB*NR) {
        const float* k = camK + t*9;
        const float* w = camW + t*12;   // rows: [R[i][0..2], t[i]]
        float R[9], tv[3];
        #pragma unroll
        for (int i = 0; i < 3; i++) {
            R[i*3+0] = w[i*4+0];
            R[i*3+1] = w[i*4+1];
            R[i*3+2] = w[i*4+2];
            tv[i]    = w[i*4+3];
        }
        float iK[9], iR[9];
        inv3(k, iK);
        inv3(R, iR);
        float* o = g_renderM[t];
        #pragma unroll
        for (int i = 0; i < 3; i++) {
            #pragma unroll
            for (int j = 0; j < 3; j++)
                o[i*3+j] = iR[i*3+0]*iK[0+j] + iR[i*3+1]*iK[3+j] + iR[i*3+2]*iK[6+j];
            o[9+i] = iR[i*3+0]*tv[0] + iR[i*3+1]*tv[1] + iR[i*3+2]*tv[2];
        }
    } else if (t < NB*NR + NB*NREF) {
        int j = t - NB*NR;
        const float* k = camKr + j*9;
        const float* w = camWr + j*12;
        float* o = g_refP[j];
        #pragma unroll
        for (int i = 0; i < 3; i++) {
            #pragma unroll
            for (int c = 0; c < 3; c++)
                o[i*3+c] = k[i*3+0]*w[0*4+c] + k[i*3+1]*w[1*4+c] + k[i*3+2]*w[2*4+c];
            o[9+i] = k[i*3+0]*w[0*4+3] + k[i*3+1]*w[1*4+3] + k[i*3+2]*w[2*4+3];
        }
    }
}

// Planar (img,c,y,x) -> AoS float4 (img,y,x). Coalesced reads (3 planes) and
// fully coalesced 16B writes. Block 0 additionally computes the folded camera
// matrices (consumed only by render_kernel, which launches after this kernel).
__global__ void __launch_bounds__(256) interleave_kernel(
    const float* __restrict__ src,
    const float* __restrict__ camK,  const float* __restrict__ camW,
    const float* __restrict__ camKr, const float* __restrict__ camWr)
{
    if (blockIdx.x == 0 && threadIdx.x < NB*NR + NB*NREF)
        precompute_thread(threadIdx.x, camK, camW, camKr, camWr);

    int i = blockIdx.x * blockDim.x + threadIdx.x;
    if (i >= NIMG*HW) return;
    int img = i / HW;
    int pix = i - img*HW;
    const float* p = src + (size_t)img*3*HW + pix;
    g_img4[i] = make_float4(__ldg(p), __ldg(p + HW), __ldg(p + 2*HW), 0.0f);
}

__global__ void __launch_bounds__(256) render_kernel(
    const float* __restrict__ depth,
    const float* __restrict__ background,
    float* __restrict__ out)
{
    int idx = blockIdx.x * blockDim.x + threadIdx.x;
    if (idx >= NPIX) return;

    int pix = idx % HW;
    int cam = idx / HW;       // = b*NR + n
    int b   = cam / NR;
    int obase = cam*3*HW + pix;

    float d = depth[idx];
    if (!(d > 0.0f)) {
        out[obase]        = background[obase];
        out[obase + HW]   = background[obase + HW];
        out[obase + 2*HW] = background[obase + 2*HW];
        return;
    }

    float fx = (float)(pix % IW);
    float fy = (float)(pix / IW);
    const float* M = g_renderM[cam];
    float nd = -d;
    float px = nd*(M[0]*fx + M[1]*fy + M[2]) - M[9];
    float py = nd*(M[3]*fx + M[4]*fy + M[5]) - M[10];
    float pz = nd*(M[6]*fx + M[7]*fy + M[8]) - M[11];

    float r0 = 0.0f, r1 = 0.0f, r2 = 0.0f;

    #pragma unroll
    for (int r = 0; r < NREF; r++) {
        const float* P = g_refP[b*NREF + r];
        float qx = P[0]*px + P[1]*py + P[2]*pz + P[9];
        float qy = P[3]*px + P[4]*py + P[5]*pz + P[10];
        float qz = P[6]*px + P[7]*py + P[8]*pz + P[11];
        float iz = __frcp_rn(qz);
        float u = qx*iz;
        float v = qy*iz;

        float x0 = floorf(u);
        float y0 = floorf(v);
        float wx = u - x0;
        float wy = v - y0;
        float x1 = x0 + 1.0f;
        float y1 = y0 + 1.0f;

        // Validity as multiplicative masks -> all gathers unconditional
        // (invalid corners contribute exactly 0, same as the reference).
        float vx0 = (x0 >= 0.0f && x0 <= (float)(IW-1)) ? 1.0f : 0.0f;
        float vx1 = (x1 >= 0.0f && x1 <= (float)(IW-1)) ? 1.0f : 0.0f;
        float vy0 = (y0 >= 0.0f && y0 <= (float)(IH-1)) ? 1.0f : 0.0f;
        float vy1 = (y1 >= 0.0f && y1 <= (float)(IH-1)) ? 1.0f : 0.0f;

        float w00 = (1.0f-wx)*(1.0f-wy) * vx0*vy0;
        float w01 = wx*(1.0f-wy)        * vx1*vy0;
        float w10 = (1.0f-wx)*wy        * vx0*vy1;
        float w11 = wx*wy               * vx1*vy1;

        int xi0 = (int)fminf(fmaxf(x0, 0.0f), (float)(IW-1));
        int xi1 = (int)fminf(fmaxf(x1, 0.0f), (float)(IW-1));
        int yi0 = (int)fminf(fmaxf(y0, 0.0f), (float)(IH-1));
        int yi1 = (int)fminf(fmaxf(y1, 0.0f), (float)(IH-1));

        const float4* fm = g_img4 + (size_t)(b*NREF + r)*HW;
        float4 c00 = __ldg(fm + (yi0*IW + xi0));
        float4 c01 = __ldg(fm + (yi0*IW + xi1));
        float4 c10 = __ldg(fm + (yi1*IW + xi0));
        float4 c11 = __ldg(fm + (yi1*IW + xi1));

        r0 += w00*c00.x + w01*c01.x + w10*c10.x + w11*c11.x;
        r1 += w00*c00.y + w01*c01.y + w10*c10.y + w11*c11.y;
        r2 += w00*c00.z + w01*c01.z + w10*c10.z + w11*c11.z;
    }

    const float sc = 1.0f / (float)NREF;
    out[obase]        = r0*sc;
    out[obase + HW]   = r1*sc;
    out[obase + 2*HW] = r2*sc;
}

extern "C" void kernel_launch(void* const* d_in, const int* in_sizes, int n_in,
                              void* d_out, int out_size) {
    const float* depth      = (const float*)d_in[0];
    const float* cam_K      = (const float*)d_in[1];
    const float* cam_W      = (const float*)d_in[2];
    const float* image_ref  = (const float*)d_in[3];
    const float* background = (const float*)d_in[4];
    // d_in[5] = cube_diagonal : divide/multiply cancels, unused
    const float* cam_K_ref  = (const float*)d_in[6];
    const float* cam_W_ref  = (const float*)d_in[7];

    interleave_kernel<<<(NIMG*HW + 255) / 256, 256>>>(image_ref, cam_K, cam_W,
                                                      cam_K_ref, cam_W_ref);
    render_kernel<<<(NPIX + 255) / 256, 256>>>(depth, background, (float*)d_out);
}

// round 9
// speedup vs baseline: 1.1150x; 1.1150x over previous
#include <cuda_runtime.h>
#include <cuda_fp16.h>

#define NB 4
#define NR 2
#define NREF 4
#define IH 320
#define IW 320
#define HW (IH*IW)
#define NPIX (NB*NR*HW)
#define NIMG (NB*NREF)

// Per-render-camera: M = inv(R)*inv(K) (9 floats) then v = inv(R)*t (3 floats)
__device__ float g_renderM[NB*NR][12];
// Per-(b,ref): P = K_ref*R_ref (9) then s = K_ref*t_ref (3)
__device__ float g_refP[NB*NREF][12];
// Channel-interleaved fp16 copy of image_ref: (img, y, x) -> {h2(r,g), h(b), pad}
// 8 bytes per texel; one aligned 8B load per bilinear corner.
__device__ uint2 g_imgh[NIMG*HW];

__device__ __forceinline__ void inv3(const float* a, float* o) {
    float c00 = a[4]*a[8] - a[5]*a[7];
    float c10 = a[5]*a[6] - a[3]*a[8];
    float c20 = a[3]*a[7] - a[4]*a[6];
    float det = a[0]*c00 + a[1]*c10 + a[2]*c20;
    float id  = 1.0f/det;
    o[0] = c00*id;
    o[1] = (a[2]*a[7] - a[1]*a[8])*id;
    o[2] = (a[1]*a[5] - a[2]*a[4])*id;
    o[3] = c10*id;
    o[4] = (a[0]*a[8] - a[2]*a[6])*id;
    o[5] = (a[2]*a[3] - a[0]*a[5])*id;
    o[6] = c20*id;
    o[7] = (a[1]*a[6] - a[0]*a[7])*id;
    o[8] = (a[0]*a[4] - a[1]*a[3])*id;
}

__device__ __forceinline__ void precompute_thread(
    int t,
    const float* __restrict__ camK,  const float* __restrict__ camW,
    const float* __restrict__ camKr, const float* __restrict__ camWr)
{
    if (t < NB*NR) {
        const float* k = camK + t*9;
        const float* w = camW + t*12;   // rows: [R[i][0..2], t[i]]
        float R[9], tv[3];
        #pragma unroll
        for (int i = 0; i < 3; i++) {
            R[i*3+0] = w[i*4+0];
            R[i*3+1] = w[i*4+1];
            R[i*3+2] = w[i*4+2];
            tv[i]    = w[i*4+3];
        }
        float iK[9], iR[9];
        inv3(k, iK);
        inv3(R, iR);
        float* o = g_renderM[t];
        #pragma unroll
        for (int i = 0; i < 3; i++) {
            #pragma unroll
            for (int j = 0; j < 3; j++)
                o[i*3+j] = iR[i*3+0]*iK[0+j] + iR[i*3+1]*iK[3+j] + iR[i*3+2]*iK[6+j];
            o[9+i] = iR[i*3+0]*tv[0] + iR[i*3+1]*tv[1] + iR[i*3+2]*tv[2];
        }
    } else if (t < NB*NR + NB*NREF) {
        int j = t - NB*NR;
        const float* k = camKr + j*9;
        const float* w = camWr + j*12;
        float* o = g_refP[j];
        #pragma unroll
        for (int i = 0; i < 3; i++) {
            #pragma unroll
            for (int c = 0; c < 3; c++)
                o[i*3+c] = k[i*3+0]*w[0*4+c] + k[i*3+1]*w[1*4+c] + k[i*3+2]*w[2*4+c];
            o[9+i] = k[i*3+0]*w[0*4+3] + k[i*3+1]*w[1*4+3] + k[i*3+2]*w[2*4+3];
        }
    }
}

// Planar f32 (img,c,y,x) -> AoS fp16 (img,y,x) {r,g,b,pad}. Coalesced reads,
// fully coalesced 8B writes. Block 0 additionally computes the folded camera
// matrices (consumed only by render_kernel, which launches after this kernel).
__global__ void __launch_bounds__(256) interleave_kernel(
    const float* __restrict__ src,
    const float* __restrict__ camK,  const float* __restrict__ camW,
    const float* __restrict__ camKr, const float* __restrict__ camWr)
{
    if (blockIdx.x == 0 && threadIdx.x < NB*NR + NB*NREF)
        precompute_thread(threadIdx.x, camK, camW, camKr, camWr);

    int i = blockIdx.x * blockDim.x + threadIdx.x;
    if (i >= NIMG*HW) return;
    int img = i / HW;
    int pix = i - img*HW;
    const float* p = src + (size_t)img*3*HW + pix;
    __half2 rg = __floats2half2_rn(__ldg(p), __ldg(p + HW));
    __half2 b0 = __floats2half2_rn(__ldg(p + 2*HW), 0.0f);
    uint2 o;
    o.x = *reinterpret_cast<const unsigned int*>(&rg);
    o.y = *reinterpret_cast<const unsigned int*>(&b0);
    g_imgh[i] = o;
}

__global__ void __launch_bounds__(256) render_kernel(
    const float* __restrict__ depth,
    const float* __restrict__ background,
    float* __restrict__ out)
{
    int idx = blockIdx.x * blockDim.x + threadIdx.x;
    if (idx >= NPIX) return;

    int pix = idx % HW;
    int cam = idx / HW;       // = b*NR + n
    int b   = cam / NR;
    int obase = cam*3*HW + pix;

    float d = depth[idx];
    if (!(d > 0.0f)) {
        out[obase]        = background[obase];
        out[obase + HW]   = background[obase + HW];
        out[obase + 2*HW] = background[obase + 2*HW];
        return;
    }

    float fx = (float)(pix % IW);
    float fy = (float)(pix / IW);
    const float* M = g_renderM[cam];
    float nd = -d;
    float px = nd*(M[0]*fx + M[1]*fy + M[2]) - M[9];
    float py = nd*(M[3]*fx + M[4]*fy + M[5]) - M[10];
    float pz = nd*(M[6]*fx + M[7]*fy + M[8]) - M[11];

    float r0 = 0.0f, r1 = 0.0f, r2 = 0.0f;

    #pragma unroll
    for (int r = 0; r < NREF; r++) {
        const float* P = g_refP[b*NREF + r];
        float qx = P[0]*px + P[1]*py + P[2]*pz + P[9];
        float qy = P[3]*px + P[4]*py + P[5]*pz + P[10];
        float qz = P[6]*px + P[7]*py + P[8]*pz + P[11];
        float iz = __frcp_rn(qz);
        float u = qx*iz;
        float v = qy*iz;

        float x0 = floorf(u);
        float y0 = floorf(v);
        float wx = u - x0;
        float wy = v - y0;
        float x1 = x0 + 1.0f;
        float y1 = y0 + 1.0f;

        // Validity as multiplicative masks -> all gathers unconditional
        // (invalid corners contribute exactly 0, same as the reference).
        float vx0 = (x0 >= 0.0f && x0 <= (float)(IW-1)) ? 1.0f : 0.0f;
        float vx1 = (x1 >= 0.0f && x1 <= (float)(IW-1)) ? 1.0f : 0.0f;
        float vy0 = (y0 >= 0.0f && y0 <= (float)(IH-1)) ? 1.0f : 0.0f;
        float vy1 = (y1 >= 0.0f && y1 <= (float)(IH-1)) ? 1.0f : 0.0f;

        float w00 = (1.0f-wx)*(1.0f-wy) * vx0*vy0;
        float w01 = wx*(1.0f-wy)        * vx1*vy0;
        float w10 = (1.0f-wx)*wy        * vx0*vy1;
        float w11 = wx*wy               * vx1*vy1;

        int xi0 = (int)fminf(fmaxf(x0, 0.0f), (float)(IW-1));
        int xi1 = (int)fminf(fmaxf(x1, 0.0f), (float)(IW-1));
        int yi0 = (int)fminf(fmaxf(y0, 0.0f), (float)(IH-1));
        int yi1 = (int)fminf(fmaxf(y1, 0.0f), (float)(IH-1));

        const uint2* fm = g_imgh + (size_t)(b*NREF + r)*HW;
        uint2 c00 = __ldg(fm + (yi0*IW + xi0));
        uint2 c01 = __ldg(fm + (yi0*IW + xi1));
        uint2 c10 = __ldg(fm + (yi1*IW + xi0));
        uint2 c11 = __ldg(fm + (yi1*IW + xi1));

        float2 rg00 = __half22float2(*reinterpret_cast<__half2*>(&c00.x));
        float2 rg01 = __half22float2(*reinterpret_cast<__half2*>(&c01.x));
        float2 rg10 = __half22float2(*reinterpret_cast<__half2*>(&c10.x));
        float2 rg11 = __half22float2(*reinterpret_cast<__half2*>(&c11.x));
        float b00 = __low2float(*reinterpret_cast<__half2*>(&c00.y));
        float b01 = __low2float(*reinterpret_cast<__half2*>(&c01.y));
        float b10 = __low2float(*reinterpret_cast<__half2*>(&c10.y));
        float b11 = __low2float(*reinterpret_cast<__half2*>(&c11.y));

        r0 += w00*rg00.x + w01*rg01.x + w10*rg10.x + w11*rg11.x;
        r1 += w00*rg00.y + w01*rg01.y + w10*rg10.y + w11*rg11.y;
        r2 += w00*b00   + w01*b01   + w10*b10   + w11*b11;
    }

    const float sc = 1.0f / (float)NREF;
    out[obase]        = r0*sc;
    out[obase + HW]   = r1*sc;
    out[obase + 2*HW] = r2*sc;
}

extern "C" void kernel_launch(void* const* d_in, const int* in_sizes, int n_in,
                              void* d_out, int out_size) {
    const float* depth      = (const float*)d_in[0];
    const float* cam_K      = (const float*)d_in[1];
    const float* cam_W      = (const float*)d_in[2];
    const float* image_ref  = (const float*)d_in[3];
    const float* background = (const float*)d_in[4];
    // d_in[5] = cube_diagonal : divide/multiply cancels, unused
    const float* cam_K_ref  = (const float*)d_in[6];
    const float* cam_W_ref  = (const float*)d_in[7];

    interleave_kernel<<<(NIMG*HW + 255) / 256, 256>>>(image_ref, cam_K, cam_W,
                                                      cam_K_ref, cam_W_ref);
    render_kernel<<<(NPIX + 255) / 256, 256>>>(depth, background, (float*)d_out);
}

// round 12
// speedup vs baseline: 1.2626x; 1.1323x over previous
#include <cuda_runtime.h>
#include <cuda_fp16.h>

#define NB 4
#define NR 2
#define NREF 4
#define IH 320
#define IW 320
#define HW (IH*IW)
#define NPIX (NB*NR*HW)
#define NIMG (NB*NREF)

// Per-render-camera: M = inv(R)*inv(K) (9 floats) then v = inv(R)*t (3 floats)
__device__ float g_renderM[NB*NR][12];
// Per-(b,ref): P = K_ref*R_ref (9) then s = K_ref*t_ref (3)
__device__ float g_refP[NB*NREF][12];
// Paired fp16 texels: entry (img,y,x) = {rg(x), b(x)|0, rg(x+1c), b(x+1c)|0}
// where x+1c = min(x+1, IW-1). One aligned 16B load covers both x-corners
// of a bilinear row.
__device__ uint4 g_imgp[NIMG*HW];

__device__ __forceinline__ void inv3(const float* a, float* o) {
    float c00 = a[4]*a[8] - a[5]*a[7];
    float c10 = a[5]*a[6] - a[3]*a[8];
    float c20 = a[3]*a[7] - a[4]*a[6];
    float det = a[0]*c00 + a[1]*c10 + a[2]*c20;
    float id  = 1.0f/det;
    o[0] = c00*id;
    o[1] = (a[2]*a[7] - a[1]*a[8])*id;
    o[2] = (a[1]*a[5] - a[2]*a[4])*id;
    o[3] = c10*id;
    o[4] = (a[0]*a[8] - a[2]*a[6])*id;
    o[5] = (a[2]*a[3] - a[0]*a[5])*id;
    o[6] = c20*id;
    o[7] = (a[1]*a[6] - a[0]*a[7])*id;
    o[8] = (a[0]*a[4] - a[1]*a[3])*id;
}

__device__ __forceinline__ void precompute_thread(
    int t,
    const float* __restrict__ camK,  const float* __restrict__ camW,
    const float* __restrict__ camKr, const float* __restrict__ camWr)
{
    if (t < NB*NR) {
        const float* k = camK + t*9;
        const float* w = camW + t*12;   // rows: [R[i][0..2], t[i]]
        float R[9], tv[3];
        #pragma unroll
        for (int i = 0; i < 3; i++) {
            R[i*3+0] = w[i*4+0];
            R[i*3+1] = w[i*4+1];
            R[i*3+2] = w[i*4+2];
            tv[i]    = w[i*4+3];
        }
        float iK[9], iR[9];
        inv3(k, iK);
        inv3(R, iR);
        float* o = g_renderM[t];
        #pragma unroll
        for (int i = 0; i < 3; i++) {
            #pragma unroll
            for (int j = 0; j < 3; j++)
                o[i*3+j] = iR[i*3+0]*iK[0+j] + iR[i*3+1]*iK[3+j] + iR[i*3+2]*iK[6+j];
            o[9+i] = iR[i*3+0]*tv[0] + iR[i*3+1]*tv[1] + iR[i*3+2]*tv[2];
        }
    } else if (t < NB*NR + NB*NREF) {
        int j = t - NB*NR;
        const float* k = camKr + j*9;
        const float* w = camWr + j*12;
        float* o = g_refP[j];
        #pragma unroll
        for (int i = 0; i < 3; i++) {
            #pragma unroll
            for (int c = 0; c < 3; c++)
                o[i*3+c] = k[i*3+0]*w[0*4+c] + k[i*3+1]*w[1*4+c] + k[i*3+2]*w[2*4+c];
            o[9+i] = k[i*3+0]*w[0*4+3] + k[i*3+1]*w[1*4+3] + k[i*3+2]*w[2*4+3];
        }
    }
}

// Planar f32 (img,c,y,x) -> paired fp16 AoS: each entry holds texels x and
// min(x+1, IW-1). Reads overlap (L1/L2-absorbed), writes fully coalesced 16B.
// Block 0 additionally computes the folded camera matrices (consumed only by
// render_kernel, which launches after this kernel).
__global__ void __launch_bounds__(256) interleave_kernel(
    const float* __restrict__ src,
    const float* __restrict__ camK,  const float* __restrict__ camW,
    const float* __restrict__ camKr, const float* __restrict__ camWr)
{
    if (blockIdx.x == 0 && threadIdx.x < NB*NR + NB*NREF)
        precompute_thread(threadIdx.x, camK, camW, camKr, camWr);

    int i = blockIdx.x * blockDim.x + threadIdx.x;
    if (i >= NIMG*HW) return;
    int img = i / HW;
    int pix = i - img*HW;
    int x   = pix % IW;
    int dx  = (x < IW-1) ? 1 : 0;
    const float* p  = src + (size_t)img*3*HW + pix;
    const float* p1 = p + dx;
    __half2 rg0 = __floats2half2_rn(__ldg(p),        __ldg(p + HW));
    __half2 b0  = __floats2half2_rn(__ldg(p + 2*HW), 0.0f);
    __half2 rg1 = __floats2half2_rn(__ldg(p1),        __ldg(p1 + HW));
    __half2 b1  = __floats2half2_rn(__ldg(p1 + 2*HW), 0.0f);
    uint4 o;
    o.x = *reinterpret_cast<const unsigned int*>(&rg0);
    o.y = *reinterpret_cast<const unsigned int*>(&b0);
    o.z = *reinterpret_cast<const unsigned int*>(&rg1);
    o.w = *reinterpret_cast<const unsigned int*>(&b1);
    g_imgp[i] = o;
}

__device__ __forceinline__ float2 h2f2(unsigned int u) {
    return __half22float2(*reinterpret_cast<__half2*>(&u));
}
__device__ __forceinline__ float h2lo(unsigned int u) {
    return __low2float(*reinterpret_cast<__half2*>(&u));
}

__global__ void __launch_bounds__(256) render_kernel(
    const float* __restrict__ depth,
    const float* __restrict__ background,
    float* __restrict__ out)
{
    int idx = blockIdx.x * blockDim.x + threadIdx.x;
    if (idx >= NPIX) return;

    int pix = idx % HW;
    int cam = idx / HW;       // = b*NR + n
    int b   = cam / NR;
    int obase = cam*3*HW + pix;

    float d = depth[idx];
    if (!(d > 0.0f)) {
        out[obase]        = background[obase];
        out[obase + HW]   = background[obase + HW];
        out[obase + 2*HW] = background[obase + 2*HW];
        return;
    }

    float fx = (float)(pix % IW);
    float fy = (float)(pix / IW);
    const float* M = g_renderM[cam];
    float nd = -d;
    float px = nd*(M[0]*fx + M[1]*fy + M[2]) - M[9];
    float py = nd*(M[3]*fx + M[4]*fy + M[5]) - M[10];
    float pz = nd*(M[6]*fx + M[7]*fy + M[8]) - M[11];

    float r0 = 0.0f, r1 = 0.0f, r2 = 0.0f;

    #pragma unroll
    for (int r = 0; r < NREF; r++) {
        const float* P = g_refP[b*NREF + r];
        float qx = P[0]*px + P[1]*py + P[2]*pz + P[9];
        float qy = P[3]*px + P[4]*py + P[5]*pz + P[10];
        float qz = P[6]*px + P[7]*py + P[8]*pz + P[11];
        float iz = __frcp_rn(qz);
        float u = qx*iz;
        float v = qy*iz;

        float x0 = floorf(u);
        float y0 = floorf(v);
        float wx = u - x0;
        float wy = v - y0;
        float x1 = x0 + 1.0f;
        float y1 = y0 + 1.0f;

        // Validity as multiplicative masks -> all gathers unconditional
        // (invalid corners contribute exactly 0, same as the reference).
        float vx0 = (x0 >= 0.0f && x0 <= (float)(IW-1)) ? 1.0f : 0.0f;
        float vx1 = (x1 >= 0.0f && x1 <= (float)(IW-1)) ? 1.0f : 0.0f;
        float vy0 = (y0 >= 0.0f && y0 <= (float)(IH-1)) ? 1.0f : 0.0f;
        float vy1 = (y1 >= 0.0f && y1 <= (float)(IH-1)) ? 1.0f : 0.0f;

        float w00 = (1.0f-wx)*(1.0f-wy) * vx0*vy0;
        float w01 = wx*(1.0f-wy)        * vx1*vy0;
        float w10 = (1.0f-wx)*wy        * vx0*vy1;
        float w11 = wx*wy               * vx1*vy1;

        int xi0 = (int)fminf(fmaxf(x0, 0.0f), (float)(IW-1));
        int xi1 = (int)fminf(fmaxf(x1, 0.0f), (float)(IW-1));
        int yi0 = (int)fminf(fmaxf(y0, 0.0f), (float)(IH-1));
        int yi1 = (int)fminf(fmaxf(y1, 0.0f), (float)(IH-1));

        const uint4* fm = g_imgp + (size_t)(b*NREF + r)*HW;
        // One 16B load per bilinear row: lo half = texel xi0, hi half = texel
        // min(xi0+1, IW-1). Corner 1 selects hi/lo by whether xi1 != xi0,
        // which matches the clamped-index semantics exactly.
        uint4 cA = __ldg(fm + (yi0*IW + xi0));   // row y0
        uint4 cB = __ldg(fm + (yi1*IW + xi0));   // row y1
        bool dsel = (xi1 != xi0);
        unsigned int rgA1 = dsel ? cA.z : cA.x;
        unsigned int bA1  = dsel ? cA.w : cA.y;
        unsigned int rgB1 = dsel ? cB.z : cB.x;
        unsigned int bB1  = dsel ? cB.w : cB.y;

        float2 rg00 = h2f2(cA.x);
        float2 rg01 = h2f2(rgA1);
        float2 rg10 = h2f2(cB.x);
        float2 rg11 = h2f2(rgB1);
        float b00 = h2lo(cA.y);
        float b01 = h2lo(bA1);
        float b10 = h2lo(cB.y);
        float b11 = h2lo(bB1);

        r0 += w00*rg00.x + w01*rg01.x + w10*rg10.x + w11*rg11.x;
        r1 += w00*rg00.y + w01*rg01.y + w10*rg10.y + w11*rg11.y;
        r2 += w00*b00   + w01*b01   + w10*b10   + w11*b11;
    }

    const float sc = 1.0f / (float)NREF;
    out[obase]        = r0*sc;
    out[obase + HW]   = r1*sc;
    out[obase + 2*HW] = r2*sc;
}

extern "C" void kernel_launch(void* const* d_in, const int* in_sizes, int n_in,
                              void* d_out, int out_size) {
    const float* depth      = (const float*)d_in[0];
    const float* cam_K      = (const float*)d_in[1];
    const float* cam_W      = (const float*)d_in[2];
    const float* image_ref  = (const float*)d_in[3];
    const float* background = (const float*)d_in[4];
    // d_in[5] = cube_diagonal : divide/multiply cancels, unused
    const float* cam_K_ref  = (const float*)d_in[6];
    const float* cam_W_ref  = (const float*)d_in[7];

    interleave_kernel<<<(NIMG*HW + 255) / 256, 256>>>(image_ref, cam_K, cam_W,
                                                      cam_K_ref, cam_W_ref);
    render_kernel<<<(NPIX + 255) / 256, 256>>>(depth, background, (float*)d_out);
}